// round 2
// baseline (speedup 1.0000x reference)
#include <cuda_runtime.h>
#include <math.h>

#define B_   4
#define NM_  128
#define PS_  16
#define NP_  1024
#define D_   1024
#define H_   16
#define DH_  64
#define L_   12
#define FF_  4096
#define S_   1025    // NP + 1 (cls)

// ---------------- scratch (device globals; no allocation allowed) ----------------
__device__ float g_patches[(size_t)B_ * NP_ * (NM_ * PS_)];   // [4096, 2048]
__device__ float g_pe     [(size_t)B_ * NP_ * D_];            // patch embed pre-LN
__device__ float g_h      [(size_t)B_ * S_ * D_];             // residual stream
__device__ float g_y      [(size_t)B_ * S_ * D_];             // ln output
__device__ float g_q      [(size_t)B_ * S_ * D_];
__device__ float g_k      [(size_t)B_ * S_ * D_];
__device__ float g_v      [(size_t)B_ * S_ * D_];
__device__ float g_o      [(size_t)B_ * S_ * D_];
__device__ float g_sc     [(size_t)B_ * H_ * S_ * S_];        // attention scores (269 MB)
__device__ float g_a1     [(size_t)B_ * S_ * FF_];
__device__ float g_a3     [(size_t)B_ * S_ * FF_];
__device__ float g_cos    [S_ * (DH_ / 2)];
__device__ float g_sin    [S_ * (DH_ / 2)];

// ---------------- generic tiled fp32 GEMM ----------------
// C = alpha * A @ op(B) [+ bias] [+ C_old]
// op(B) = B[K,N] if !TRANSB, else B[N,K] accessed transposed.
// Two-level batching: z -> (bb = z/nH, hh = z%nH); pointer += bb*s?b + hh*s?h.
template<bool TRANSB, bool ACCUM, bool BIAS>
__global__ __launch_bounds__(256) void gemm_kernel(
    const float* __restrict__ A, const float* __restrict__ B,
    const float* __restrict__ bias, float* __restrict__ C,
    int M, int N, int K, int lda, int ldb, int ldc,
    int nH,
    long long sAb, long long sAh, long long sBb, long long sBh,
    long long sCb, long long sCh, float alpha)
{
    __shared__ float As[64][17];
    __shared__ float Bs[16][65];

    int bz = blockIdx.z;
    int bb = bz / nH, hh = bz % nH;
    const float* Ap = A + (long long)bb * sAb + (long long)hh * sAh;
    const float* Bp = B + (long long)bb * sBb + (long long)hh * sBh;
    float*       Cp = C + (long long)bb * sCb + (long long)hh * sCh;

    int rowBase = blockIdx.y * 64;
    int colBase = blockIdx.x * 64;
    int tx = threadIdx.x, ty = threadIdx.y;
    int tid = ty * 16 + tx;

    float acc[4][4] = {};

    for (int k0 = 0; k0 < K; k0 += 16) {
        #pragma unroll
        for (int i = 0; i < 4; i++) {
            int idx = tid + i * 256;
            int r = idx >> 4, kk = idx & 15;
            int gr = rowBase + r, gk = k0 + kk;
            As[r][kk] = (gr < M && gk < K) ? Ap[(long long)gr * lda + gk] : 0.f;
        }
        #pragma unroll
        for (int i = 0; i < 4; i++) {
            int idx = tid + i * 256;
            if (!TRANSB) {
                int kk = idx >> 6, c = idx & 63;
                int gk = k0 + kk, gc = colBase + c;
                Bs[kk][c] = (gk < K && gc < N) ? Bp[(long long)gk * ldb + gc] : 0.f;
            } else {
                int c = idx >> 4, kk = idx & 15;
                int gk = k0 + kk, gc = colBase + c;
                Bs[kk][c] = (gk < K && gc < N) ? Bp[(long long)gc * ldb + gk] : 0.f;
            }
        }
        __syncthreads();

        #pragma unroll
        for (int kk = 0; kk < 16; kk++) {
            float ra[4], rb[4];
            #pragma unroll
            for (int i = 0; i < 4; i++) ra[i] = As[ty * 4 + i][kk];
            #pragma unroll
            for (int j = 0; j < 4; j++) rb[j] = Bs[kk][tx * 4 + j];
            #pragma unroll
            for (int i = 0; i < 4; i++)
                #pragma unroll
                for (int j = 0; j < 4; j++)
                    acc[i][j] = fmaf(ra[i], rb[j], acc[i][j]);
        }
        __syncthreads();
    }

    #pragma unroll
    for (int i = 0; i < 4; i++) {
        int gr = rowBase + ty * 4 + i;
        if (gr >= M) continue;
        #pragma unroll
        for (int j = 0; j < 4; j++) {
            int gc = colBase + tx * 4 + j;
            if (gc >= N) continue;
            float val = acc[i][j] * alpha;
            if (BIAS)  val += bias[gc];
            if (ACCUM) val += Cp[(long long)gr * ldc + gc];
            Cp[(long long)gr * ldc + gc] = val;
        }
    }
}

// ---------------- layernorm (D = 1024, blockDim = 256) ----------------
__device__ __forceinline__ void ln_row_1024(const float* __restrict__ x,
                                            float* __restrict__ y,
                                            const float* __restrict__ gw,
                                            const float* __restrict__ bw)
{
    __shared__ float sh1[32], sh2[32];
    float v[4];
    float s = 0.f, ss = 0.f;
    #pragma unroll
    for (int i = 0; i < 4; i++) {
        v[i] = x[threadIdx.x + i * 256];
        s += v[i]; ss += v[i] * v[i];
    }
    #pragma unroll
    for (int o = 16; o > 0; o >>= 1) {
        s  += __shfl_down_sync(0xffffffffu, s,  o);
        ss += __shfl_down_sync(0xffffffffu, ss, o);
    }
    int lane = threadIdx.x & 31, w = threadIdx.x >> 5;
    if (lane == 0) { sh1[w] = s; sh2[w] = ss; }
    __syncthreads();
    if (w == 0) {
        s  = lane < 8 ? sh1[lane] : 0.f;
        ss = lane < 8 ? sh2[lane] : 0.f;
        #pragma unroll
        for (int o = 4; o > 0; o >>= 1) {
            s  += __shfl_down_sync(0xffffffffu, s,  o);
            ss += __shfl_down_sync(0xffffffffu, ss, o);
        }
        if (lane == 0) { sh1[0] = s; sh2[0] = ss; }
    }
    __syncthreads();
    float mu  = sh1[0] * (1.f / D_);
    float var = sh2[0] * (1.f / D_) - mu * mu;
    float inv = rsqrtf(var + 1e-5f);
    #pragma unroll
    for (int i = 0; i < 4; i++) {
        int c = threadIdx.x + i * 256;
        y[c] = (v[i] - mu) * inv * gw[c] + bw[c];
    }
}

__global__ void layernorm_kernel(const float* __restrict__ in, float* __restrict__ out,
                                 const float* __restrict__ gw, const float* __restrict__ bw)
{
    long long row = blockIdx.x;
    ln_row_1024(in + row * D_, out + row * D_, gw, bw);
}

// LN the patch-embed rows and scatter into h at position (b, 1+p)
__global__ void patch_ln_kernel(const float* __restrict__ pe, float* __restrict__ h,
                                const float* __restrict__ gw, const float* __restrict__ bw)
{
    int row = blockIdx.x;                  // 0..4095 = b*1024 + p
    int b = row >> 10, p = row & 1023;
    ln_row_1024(pe + (long long)row * D_,
                h + ((long long)b * S_ + 1 + p) * D_, gw, bw);
}

// ---------------- misc elementwise kernels ----------------
__global__ void patchify_kernel(const float* __restrict__ x, float* __restrict__ p)
{
    long long t = (long long)blockIdx.x * blockDim.x + threadIdx.x;
    const long long total = (long long)B_ * NP_ * NM_ * PS_;
    if (t >= total) return;
    int c   = (int)(t & 2047);             // column within patch row (= m*16 + tt)
    long long bp = t >> 11;
    int pidx = (int)(bp & (NP_ - 1));
    int b    = (int)(bp >> 10);
    int m  = c >> 4;
    int tt = c & 15;
    p[t] = x[((long long)b * NM_ + m) * (PS_ * NP_) + (long long)pidx * PS_ + tt];
}

__global__ void cls_kernel(float* __restrict__ h, const float* __restrict__ cls)
{
    int t = blockIdx.x * blockDim.x + threadIdx.x;
    if (t >= B_ * D_) return;
    int b = t >> 10, i = t & 1023;
    h[(long long)b * S_ * D_ + i] = cls[i];
}

__global__ void rope_table_kernel(float* __restrict__ ct, float* __restrict__ st)
{
    int idx = blockIdx.x * blockDim.x + threadIdx.x;
    if (idx >= S_ * (DH_ / 2)) return;
    int i = idx & 31, s = idx >> 5;
    double invf = pow(10000.0, -(double)(2 * i) / (double)DH_);
    double ang  = (double)s * invf;
    ct[idx] = (float)cos(ang);
    st[idx] = (float)sin(ang);
}

__global__ void rope_kernel(float* __restrict__ q, float* __restrict__ k,
                            const float* __restrict__ ct, const float* __restrict__ st)
{
    long long t = (long long)blockIdx.x * blockDim.x + threadIdx.x;
    const long long total = (long long)B_ * S_ * H_ * (DH_ / 2);
    if (t >= total) return;
    int i = (int)(t & 31);
    long long r = t >> 5;
    int h = (int)(r & (H_ - 1));
    long long bs = r >> 4;                 // b*S + s
    int s = (int)(bs % S_);
    float c  = ct[s * 32 + i];
    float sn = st[s * 32 + i];
    long long base = bs * D_ + (long long)h * DH_;
    float q0 = q[base + i], q1 = q[base + i + 32];
    q[base + i]      = q0 * c - q1 * sn;
    q[base + i + 32] = q1 * c + q0 * sn;
    float k0 = k[base + i], k1 = k[base + i + 32];
    k[base + i]      = k0 * c - k1 * sn;
    k[base + i + 32] = k1 * c + k0 * sn;
}

__global__ void softmax_kernel(float* __restrict__ sc)
{
    __shared__ float sh[32];
    long long row = blockIdx.x;
    float* x = sc + row * (long long)S_;
    float lv[5];
    float m = -1e30f;
    #pragma unroll
    for (int j = 0; j < 5; j++) {
        int c = threadIdx.x + j * 256;
        lv[j] = (c < S_) ? x[c] : -1e30f;
        m = fmaxf(m, lv[j]);
    }
    #pragma unroll
    for (int o = 16; o > 0; o >>= 1) m = fmaxf(m, __shfl_xor_sync(0xffffffffu, m, o));
    int lane = threadIdx.x & 31, w = threadIdx.x >> 5;
    if (lane == 0) sh[w] = m;
    __syncthreads();
    if (w == 0) {
        float t = lane < 8 ? sh[lane] : -1e30f;
        #pragma unroll
        for (int o = 4; o > 0; o >>= 1) t = fmaxf(t, __shfl_xor_sync(0xffffffffu, t, o));
        if (lane == 0) sh[0] = t;
    }
    __syncthreads();
    m = sh[0];
    __syncthreads();
    float s = 0.f;
    #pragma unroll
    for (int j = 0; j < 5; j++) {
        int c = threadIdx.x + j * 256;
        if (c < S_) { lv[j] = expf(lv[j] - m); s += lv[j]; }
    }
    #pragma unroll
    for (int o = 16; o > 0; o >>= 1) s += __shfl_xor_sync(0xffffffffu, s, o);
    if (lane == 0) sh[w] = s;
    __syncthreads();
    if (w == 0) {
        float t = lane < 8 ? sh[lane] : 0.f;
        #pragma unroll
        for (int o = 4; o > 0; o >>= 1) t += __shfl_xor_sync(0xffffffffu, t, o);
        if (lane == 0) sh[0] = t;
    }
    __syncthreads();
    float inv = 1.f / sh[0];
    #pragma unroll
    for (int j = 0; j < 5; j++) {
        int c = threadIdx.x + j * 256;
        if (c < S_) x[c] = lv[j] * inv;
    }
}

__global__ void swiglu_kernel(float* __restrict__ a1, const float* __restrict__ a3)
{
    long long t = (long long)blockIdx.x * blockDim.x + threadIdx.x;
    const long long total = (long long)B_ * S_ * FF_;
    if (t >= total) return;
    float x = a1[t];
    float sig = 1.f / (1.f + expf(-x));
    a1[t] = x * sig * a3[t];
}

// ---------------- host side ----------------
static inline void run_gemm(const float* A, const float* B, const float* bias, float* C,
                            int M, int N, int K, int lda, int ldb, int ldc,
                            int batch, int nH,
                            long long sAb, long long sAh, long long sBb, long long sBh,
                            long long sCb, long long sCh,
                            float alpha, bool transB, bool accum)
{
    dim3 grid((N + 63) / 64, (M + 63) / 64, batch), block(16, 16);
    bool hb = (bias != nullptr);
#define GL(TB, AC, BI) gemm_kernel<TB, AC, BI><<<grid, block>>>(A, B, bias, C, M, N, K, lda, ldb, ldc, nH, sAb, sAh, sBb, sBh, sCb, sCh, alpha)
    if      ( transB &&  accum &&  hb) GL(true,  true,  true );
    else if ( transB &&  accum && !hb) GL(true,  true,  false);
    else if ( transB && !accum &&  hb) GL(true,  false, true );
    else if ( transB && !accum && !hb) GL(true,  false, false);
    else if (!transB &&  accum &&  hb) GL(false, true,  true );
    else if (!transB &&  accum && !hb) GL(false, true,  false);
    else if (!transB && !accum &&  hb) GL(false, false, true );
    else                               GL(false, false, false);
#undef GL
}

extern "C" void kernel_launch(void* const* d_in, const int* in_sizes, int n_in,
                              void* d_out, int out_size)
{
    (void)in_sizes; (void)n_in; (void)out_size;
    const float* x        = (const float*)d_in[0];
    const float* patch_w  = (const float*)d_in[1];
    const float* patch_b  = (const float*)d_in[2];
    const float* pln_g    = (const float*)d_in[3];
    const float* pln_b    = (const float*)d_in[4];
    const float* cls_tok  = (const float*)d_in[5];
    const float* ln1_g    = (const float*)d_in[6];
    const float* ln1_b    = (const float*)d_in[7];
    const float* wq       = (const float*)d_in[8];
    const float* bq       = (const float*)d_in[9];
    const float* wk       = (const float*)d_in[10];
    const float* bk       = (const float*)d_in[11];
    const float* wv       = (const float*)d_in[12];
    const float* bv       = (const float*)d_in[13];
    const float* wo       = (const float*)d_in[14];
    const float* bo       = (const float*)d_in[15];
    const float* ln2_g    = (const float*)d_in[16];
    const float* ln2_b    = (const float*)d_in[17];
    const float* w1       = (const float*)d_in[18];
    const float* b1       = (const float*)d_in[19];
    const float* w2       = (const float*)d_in[20];
    const float* b2       = (const float*)d_in[21];
    const float* w3       = (const float*)d_in[22];
    const float* b3       = (const float*)d_in[23];
    const float* lnf_g    = (const float*)d_in[24];
    const float* lnf_b    = (const float*)d_in[25];
    float* out = (float*)d_out;

    float *patches, *pe, *h, *y, *q, *k, *v, *o, *sc, *a1, *a3, *ct, *st;
    cudaGetSymbolAddress((void**)&patches, g_patches);
    cudaGetSymbolAddress((void**)&pe, g_pe);
    cudaGetSymbolAddress((void**)&h,  g_h);
    cudaGetSymbolAddress((void**)&y,  g_y);
    cudaGetSymbolAddress((void**)&q,  g_q);
    cudaGetSymbolAddress((void**)&k,  g_k);
    cudaGetSymbolAddress((void**)&v,  g_v);
    cudaGetSymbolAddress((void**)&o,  g_o);
    cudaGetSymbolAddress((void**)&sc, g_sc);
    cudaGetSymbolAddress((void**)&a1, g_a1);
    cudaGetSymbolAddress((void**)&a3, g_a3);
    cudaGetSymbolAddress((void**)&ct, g_cos);
    cudaGetSymbolAddress((void**)&st, g_sin);

    const int MR = B_ * S_;                      // 4100 rows
    const long long SD = (long long)S_ * D_;     // per-batch stride in q/k/v/h
    const long long SS = (long long)S_ * S_;     // per-head score stride

    // 1. patchify + RoPE tables
    {
        long long n = (long long)B_ * NP_ * NM_ * PS_;
        patchify_kernel<<<(int)((n + 255) / 256), 256>>>(x, patches);
    }
    rope_table_kernel<<<(S_ * 32 + 255) / 256, 256>>>(ct, st);

    // 2. patch embed: pe = patches @ patch_w + patch_b; LN -> h[:,1:,:]; cls -> h[:,0,:]
    run_gemm(patches, patch_w, patch_b, pe,
             B_ * NP_, D_, NM_ * PS_, NM_ * PS_, D_, D_,
             1, 1, 0, 0, 0, 0, 0, 0, 1.f, false, false);
    patch_ln_kernel<<<B_ * NP_, 256>>>(pe, h, pln_g, pln_b);
    cls_kernel<<<(B_ * D_ + 255) / 256, 256>>>(h, cls_tok);

    // 3. transformer layers
    const float scale = 0.125f;                  // 1/sqrt(64)
    for (int l = 0; l < L_; l++) {
        const float* Wq = wq + (size_t)l * D_ * D_;
        const float* Wk = wk + (size_t)l * D_ * D_;
        const float* Wv = wv + (size_t)l * D_ * D_;
        const float* Wo = wo + (size_t)l * D_ * D_;
        const float* W1 = w1 + (size_t)l * D_ * FF_;
        const float* W2 = w2 + (size_t)l * FF_ * D_;
        const float* W3 = w3 + (size_t)l * D_ * FF_;

        layernorm_kernel<<<MR, 256>>>(h, y, ln1_g + (size_t)l * D_, ln1_b + (size_t)l * D_);

        run_gemm(y, Wq, bq + (size_t)l * D_, q, MR, D_, D_, D_, D_, D_,
                 1, 1, 0, 0, 0, 0, 0, 0, 1.f, false, false);
        run_gemm(y, Wk, bk + (size_t)l * D_, k, MR, D_, D_, D_, D_, D_,
                 1, 1, 0, 0, 0, 0, 0, 0, 1.f, false, false);
        run_gemm(y, Wv, bv + (size_t)l * D_, v, MR, D_, D_, D_, D_, D_,
                 1, 1, 0, 0, 0, 0, 0, 0, 1.f, false, false);

        {
            long long n = (long long)B_ * S_ * H_ * (DH_ / 2);
            rope_kernel<<<(int)((n + 255) / 256), 256>>>(q, k, ct, st);
        }

        // scores[b,h] = scale * q[b,:,h*64:] @ k[b,:,h*64:]^T
        run_gemm(q, k, nullptr, sc, S_, S_, DH_, D_, D_, S_,
                 B_ * H_, H_,
                 SD, DH_, SD, DH_, (long long)H_ * SS, SS,
                 scale, true, false);

        softmax_kernel<<<B_ * H_ * S_, 256>>>(sc);

        // o[b,:,h*64:] = attn[b,h] @ v[b,:,h*64:]
        run_gemm(sc, v, nullptr, o, S_, DH_, S_, S_, D_, D_,
                 B_ * H_, H_,
                 (long long)H_ * SS, SS, SD, DH_, SD, DH_,
                 1.f, false, false);

        // h += o @ Wo + bo
        run_gemm(o, Wo, bo + (size_t)l * D_, h, MR, D_, D_, D_, D_, D_,
                 1, 1, 0, 0, 0, 0, 0, 0, 1.f, false, true);

        layernorm_kernel<<<MR, 256>>>(h, y, ln2_g + (size_t)l * D_, ln2_b + (size_t)l * D_);

        run_gemm(y, W1, b1 + (size_t)l * FF_, a1, MR, FF_, D_, D_, FF_, FF_,
                 1, 1, 0, 0, 0, 0, 0, 0, 1.f, false, false);
        run_gemm(y, W3, b3 + (size_t)l * FF_, a3, MR, FF_, D_, D_, FF_, FF_,
                 1, 1, 0, 0, 0, 0, 0, 0, 1.f, false, false);

        {
            long long n = (long long)B_ * S_ * FF_;
            swiglu_kernel<<<(int)((n + 255) / 256), 256>>>(a1, a3);
        }

        // h += (silu(a1)*a3) @ W2 + b2
        run_gemm(a1, W2, b2 + (size_t)l * D_, h, MR, D_, FF_, FF_, D_, D_,
                 1, 1, 0, 0, 0, 0, 0, 0, 1.f, false, true);
    }

    // 4. final LN -> output
    layernorm_kernel<<<MR, 256>>>(h, out, lnf_g, lnf_b);
}

// round 4
// speedup vs baseline: 2.9018x; 2.9018x over previous
#include <cuda_runtime.h>
#include <math.h>
#include <stdint.h>

#define B_   4
#define NM_  128
#define PS_  16
#define NP_  1024
#define D_   1024
#define H_   16
#define DH_  64
#define L_   12
#define FF_  4096
#define S_   1025
#define SP_  1040          // padded score row (multiple of 16 floats)

// ================= scratch =================
__device__ float g_patches[(size_t)B_ * NP_ * (NM_ * PS_)];
__device__ float g_pe     [(size_t)B_ * NP_ * D_];
__device__ float g_h      [(size_t)B_ * S_ * D_];
__device__ float g_y      [(size_t)B_ * S_ * D_];
__device__ float g_q      [(size_t)B_ * S_ * D_];
__device__ float g_k      [(size_t)B_ * S_ * D_];
__device__ float g_v      [(size_t)B_ * S_ * D_];
__device__ float g_o      [(size_t)B_ * S_ * D_];
__device__ float g_sc     [(size_t)B_ * H_ * S_ * SP_];
__device__ float g_a1     [(size_t)B_ * S_ * FF_];
__device__ float g_a3     [(size_t)B_ * S_ * FF_];
__device__ float g_cos    [S_ * (DH_ / 2)];
__device__ float g_sin    [S_ * (DH_ / 2)];
// transposed operands ([N,K] K-major)
__device__ float g_pwT [(size_t)D_ * (NM_ * PS_)];
__device__ float g_wqT [(size_t)L_ * D_ * D_];
__device__ float g_wkT [(size_t)L_ * D_ * D_];
__device__ float g_wvT [(size_t)L_ * D_ * D_];
__device__ float g_woT [(size_t)L_ * D_ * D_];
__device__ float g_w1T [(size_t)L_ * FF_ * D_];
__device__ float g_w3T [(size_t)L_ * FF_ * D_];
__device__ float g_w2T [(size_t)L_ * D_ * FF_];
__device__ float g_vT  [(size_t)B_ * H_ * DH_ * SP_];

// ================= tf32 helpers =================
__device__ __forceinline__ float f2tf32(float x) {
    uint32_t u; asm("cvt.rna.tf32.f32 %0, %1;" : "=r"(u) : "f"(x));
    return __uint_as_float(u);
}
__device__ __forceinline__ void mma8(float* c, const uint32_t* a, const uint32_t* b) {
    asm volatile(
        "mma.sync.aligned.m16n8k8.row.col.f32.tf32.tf32.f32 "
        "{%0,%1,%2,%3}, {%4,%5,%6,%7}, {%8,%9}, {%0,%1,%2,%3};"
        : "+f"(c[0]), "+f"(c[1]), "+f"(c[2]), "+f"(c[3])
        : "r"(a[0]), "r"(a[1]), "r"(a[2]), "r"(a[3]), "r"(b[0]), "r"(b[1]));
}

// ================= mma.sync tf32 GEMM =================
// C[M,N] = alpha * A[M,K](row-major, lda) @ B[N,K](K-major, ldb)^T [+bias] [+C]
// CTA tile 128x128, K-chunk 16, 8 warps (2x4), warp tile 64x32.
// SMEM holds operands in mma fragment order:
//  A: [(mtile*2+kc)][lane][reg(4)]  -> LDS.128 per fragment
//  B: [(ntile*2+kc)][lane][reg(2)]  -> LDS.64  per fragment

__device__ __forceinline__ void g_load2(const float* __restrict__ P, int ldp,
                                        int maxR, int K, int rBase, int k0,
                                        int tid, float4* out)
{
    int r0 = tid >> 2;                 // 0..63 (+64 per i)
    int gk = k0 + (tid & 3) * 4;       // 0,4,8,12 within chunk
    #pragma unroll
    for (int i = 0; i < 2; i++) {
        int gr = rBase + r0 + i * 64;
        float4 v = {0.f, 0.f, 0.f, 0.f};
        if (gr < maxR) {
            const float* p = P + (long long)gr * ldp + gk;
            if (gk + 3 < K) v = *(const float4*)p;
            else {
                if (gk     < K) v.x = p[0];
                if (gk + 1 < K) v.y = p[1];
                if (gk + 2 < K) v.z = p[2];
            }
        }
        out[i] = v;
    }
}

__device__ __forceinline__ void sts_A(float* __restrict__ As, const float4* pa, int tid)
{
    int r0  = tid >> 2;
    int ccb = (tid & 3) * 4;
    #pragma unroll
    for (int i = 0; i < 2; i++) {
        int r = r0 + i * 64;
        int mt = r >> 4, rr = r & 15;
        const float* v = (const float*)&pa[i];
        #pragma unroll
        for (int e = 0; e < 4; e++) {
            int c  = ccb + e;
            int kc = c >> 3, cc = c & 7;
            int ln  = (rr & 7) * 4 + (cc & 3);
            int reg = (rr >> 3) + 2 * (cc >> 2);
            As[((mt * 2 + kc) * 32 + ln) * 4 + reg] = f2tf32(v[e]);
        }
    }
}

__device__ __forceinline__ void sts_B(float* __restrict__ Bs, const float4* pb, int tid)
{
    int n0  = tid >> 2;
    int ccb = (tid & 3) * 4;
    #pragma unroll
    for (int i = 0; i < 2; i++) {
        int n = n0 + i * 64;
        int nt = n >> 3, nr = n & 7;
        const float* v = (const float*)&pb[i];
        #pragma unroll
        for (int e = 0; e < 4; e++) {
            int c  = ccb + e;
            int kc = c >> 3, cc = c & 7;
            int ln  = nr * 4 + (cc & 3);
            int reg = cc >> 2;
            Bs[((nt * 2 + kc) * 32 + ln) * 2 + reg] = f2tf32(v[e]);
        }
    }
}

template<bool ACCUM, bool BIAS>
__global__ __launch_bounds__(256, 2) void mma_gemm_kernel(
    const float* __restrict__ A, const float* __restrict__ B,
    const float* __restrict__ bias, float* __restrict__ C,
    int M, int N, int K, int lda, int ldb, int ldc,
    int nH,
    long long sAb, long long sAh, long long sBb, long long sBh,
    long long sCb, long long sCh, float alpha)
{
    __shared__ __align__(16) float smA[2][2048];
    __shared__ __align__(16) float smB[2][2048];

    int tid = threadIdx.x, lane = tid & 31, wid = tid >> 5;
    int warp_m = wid >> 2, warp_n = wid & 3;

    int bz = blockIdx.z;
    int bb = bz / nH, hh = bz % nH;
    const float* Ap = A + (long long)bb * sAb + (long long)hh * sAh;
    const float* Bp = B + (long long)bb * sBb + (long long)hh * sBh;
    float*       Cp = C + (long long)bb * sCb + (long long)hh * sCh;

    int rowBase = blockIdx.y * 128;
    int colBase = blockIdx.x * 128;
    int T = (K + 15) >> 4;

    float acc[4][4][4] = {};
    float4 pa[2], pb[2];

    g_load2(Ap, lda, M, K, rowBase, 0, tid, pa);
    g_load2(Bp, ldb, N, K, colBase, 0, tid, pb);
    sts_A(smA[0], pa, tid);
    sts_B(smB[0], pb, tid);

    for (int t = 0; t < T; t++) {
        __syncthreads();
        if (t + 1 < T) {
            g_load2(Ap, lda, M, K, rowBase, (t + 1) << 4, tid, pa);
            g_load2(Bp, ldb, N, K, colBase, (t + 1) << 4, tid, pb);
        }
        const float* As = smA[t & 1];
        const float* Bs = smB[t & 1];
        #pragma unroll
        for (int kc = 0; kc < 2; kc++) {
            float4 af[4]; float2 bf[4];
            #pragma unroll
            for (int mt = 0; mt < 4; mt++)
                af[mt] = *(const float4*)&As[(((warp_m * 4 + mt) * 2 + kc) * 32 + lane) * 4];
            #pragma unroll
            for (int nt = 0; nt < 4; nt++)
                bf[nt] = *(const float2*)&Bs[(((warp_n * 4 + nt) * 2 + kc) * 32 + lane) * 2];
            #pragma unroll
            for (int mt = 0; mt < 4; mt++)
                #pragma unroll
                for (int nt = 0; nt < 4; nt++)
                    mma8(acc[mt][nt], (const uint32_t*)&af[mt], (const uint32_t*)&bf[nt]);
        }
        if (t + 1 < T) {
            __syncthreads();
            sts_A(smA[(t + 1) & 1], pa, tid);
            sts_B(smB[(t + 1) & 1], pb, tid);
        }
    }

    // ---- epilogue ----
    int rw = rowBase + warp_m * 64;
    int cw = colBase + warp_n * 32;
    #pragma unroll
    for (int mt = 0; mt < 4; mt++) {
        #pragma unroll
        for (int nt = 0; nt < 4; nt++) {
            int r0 = rw + mt * 16 + (lane >> 2);
            int gc = cw + nt * 8 + (lane & 3) * 2;
            const float* cf = acc[mt][nt];
            #pragma unroll
            for (int half = 0; half < 2; half++) {
                int gr = r0 + half * 8;
                if (gr >= M) continue;
                float v0 = cf[half * 2]     * alpha;
                float v1 = cf[half * 2 + 1] * alpha;
                float* crow = Cp + (long long)gr * ldc;
                if (gc + 1 < N) {
                    if (BIAS) {
                        float2 b2 = *(const float2*)(bias + gc);
                        v0 += b2.x; v1 += b2.y;
                    }
                    if (ACCUM) {
                        float2 c2 = *(const float2*)(crow + gc);
                        v0 += c2.x; v1 += c2.y;
                    }
                    float2 o2 = {v0, v1};
                    *(float2*)(crow + gc) = o2;
                } else if (gc < N) {
                    if (BIAS)  v0 += bias[gc];
                    if (ACCUM) v0 += crow[gc];
                    crow[gc] = v0;
                }
            }
        }
    }
}

// ================= transposes =================
__global__ void transpose_kernel(const float* __restrict__ src, float* __restrict__ dst,
                                 int R, int C, long long sS, long long sD)
{
    __shared__ float t[32][33];
    const float* s = src + (long long)blockIdx.z * sS;
    float* d = dst + (long long)blockIdx.z * sD;
    int c0 = blockIdx.x * 32, r0 = blockIdx.y * 32;
    #pragma unroll
    for (int i = 0; i < 4; i++) {
        int r = r0 + threadIdx.y + i * 8, c = c0 + threadIdx.x;
        if (r < R && c < C) t[threadIdx.y + i * 8][threadIdx.x] = s[(long long)r * C + c];
    }
    __syncthreads();
    #pragma unroll
    for (int i = 0; i < 4; i++) {
        int r = c0 + threadIdx.y + i * 8, c = r0 + threadIdx.x;
        if (r < C && c < R) d[(long long)r * R + c] = t[threadIdx.x][threadIdx.y + i * 8];
    }
}

__global__ void vtrans_kernel(const float* __restrict__ v, float* __restrict__ vt)
{
    __shared__ float t[32][33];
    int z = blockIdx.z; int b = z >> 4, h = z & 15;
    int s0 = blockIdx.x * 32, j0 = blockIdx.y * 32;
    #pragma unroll
    for (int i = 0; i < 4; i++) {
        int s = s0 + threadIdx.y + i * 8, j = j0 + threadIdx.x;
        t[threadIdx.y + i * 8][threadIdx.x] =
            (s < S_) ? v[((long long)b * S_ + s) * D_ + h * DH_ + j] : 0.f;
    }
    __syncthreads();
    #pragma unroll
    for (int i = 0; i < 4; i++) {
        int j = j0 + threadIdx.y + i * 8, s = s0 + threadIdx.x;
        if (s < S_)
            vt[((long long)z * DH_ + j) * SP_ + s] = t[threadIdx.x][threadIdx.y + i * 8];
    }
}

// ================= layernorm =================
__device__ __forceinline__ void ln_row_1024(const float* __restrict__ x,
                                            float* __restrict__ y,
                                            const float* __restrict__ gw,
                                            const float* __restrict__ bw)
{
    __shared__ float sh1[32], sh2[32];
    float v[4];
    float s = 0.f, ss = 0.f;
    #pragma unroll
    for (int i = 0; i < 4; i++) {
        v[i] = x[threadIdx.x + i * 256];
        s += v[i]; ss += v[i] * v[i];
    }
    #pragma unroll
    for (int o = 16; o > 0; o >>= 1) {
        s  += __shfl_down_sync(0xffffffffu, s,  o);
        ss += __shfl_down_sync(0xffffffffu, ss, o);
    }
    int lane = threadIdx.x & 31, w = threadIdx.x >> 5;
    if (lane == 0) { sh1[w] = s; sh2[w] = ss; }
    __syncthreads();
    if (w == 0) {
        s  = lane < 8 ? sh1[lane] : 0.f;
        ss = lane < 8 ? sh2[lane] : 0.f;
        #pragma unroll
        for (int o = 4; o > 0; o >>= 1) {
            s  += __shfl_down_sync(0xffffffffu, s,  o);
            ss += __shfl_down_sync(0xffffffffu, ss, o);
        }
        if (lane == 0) { sh1[0] = s; sh2[0] = ss; }
    }
    __syncthreads();
    float mu  = sh1[0] * (1.f / D_);
    float var = sh2[0] * (1.f / D_) - mu * mu;
    float inv = rsqrtf(var + 1e-5f);
    #pragma unroll
    for (int i = 0; i < 4; i++) {
        int c = threadIdx.x + i * 256;
        y[c] = (v[i] - mu) * inv * gw[c] + bw[c];
    }
}

__global__ void layernorm_kernel(const float* __restrict__ in, float* __restrict__ out,
                                 const float* __restrict__ gw, const float* __restrict__ bw)
{
    long long row = blockIdx.x;
    ln_row_1024(in + row * D_, out + row * D_, gw, bw);
}

__global__ void patch_ln_kernel(const float* __restrict__ pe, float* __restrict__ h,
                                const float* __restrict__ gw, const float* __restrict__ bw)
{
    int row = blockIdx.x;
    int b = row >> 10, p = row & 1023;
    ln_row_1024(pe + (long long)row * D_, h + ((long long)b * S_ + 1 + p) * D_, gw, bw);
}

// ================= misc elementwise =================
__global__ void patchify_kernel(const float* __restrict__ x, float* __restrict__ p)
{
    long long t = (long long)blockIdx.x * blockDim.x + threadIdx.x;
    const long long total = (long long)B_ * NP_ * NM_ * PS_;
    if (t >= total) return;
    int c   = (int)(t & 2047);
    long long bp = t >> 11;
    int pidx = (int)(bp & (NP_ - 1));
    int b    = (int)(bp >> 10);
    int m  = c >> 4;
    int tt = c & 15;
    p[t] = x[((long long)b * NM_ + m) * (PS_ * NP_) + (long long)pidx * PS_ + tt];
}

__global__ void cls_kernel(float* __restrict__ h, const float* __restrict__ cls)
{
    int t = blockIdx.x * blockDim.x + threadIdx.x;
    if (t >= B_ * D_) return;
    int b = t >> 10, i = t & 1023;
    h[(long long)b * S_ * D_ + i] = cls[i];
}

__global__ void rope_table_kernel(float* __restrict__ ct, float* __restrict__ st)
{
    int idx = blockIdx.x * blockDim.x + threadIdx.x;
    if (idx >= S_ * (DH_ / 2)) return;
    int i = idx & 31, s = idx >> 5;
    double invf = pow(10000.0, -(double)(2 * i) / (double)DH_);
    double ang  = (double)s * invf;
    ct[idx] = (float)cos(ang);
    st[idx] = (float)sin(ang);
}

__global__ void rope_kernel(float* __restrict__ q, float* __restrict__ k,
                            const float* __restrict__ ct, const float* __restrict__ st)
{
    long long t = (long long)blockIdx.x * blockDim.x + threadIdx.x;
    const long long total = (long long)B_ * S_ * H_ * (DH_ / 2);
    if (t >= total) return;
    int i = (int)(t & 31);
    long long r = t >> 5;
    int h = (int)(r & (H_ - 1));
    long long bs = r >> 4;
    int s = (int)(bs % S_);
    float c  = ct[s * 32 + i];
    float sn = st[s * 32 + i];
    long long base = bs * D_ + (long long)h * DH_;
    float q0 = q[base + i], q1 = q[base + i + 32];
    q[base + i]      = q0 * c - q1 * sn;
    q[base + i + 32] = q1 * c + q0 * sn;
    float k0 = k[base + i], k1 = k[base + i + 32];
    k[base + i]      = k0 * c - k1 * sn;
    k[base + i + 32] = k1 * c + k0 * sn;
}

__global__ void softmax_kernel(float* __restrict__ sc)
{
    __shared__ float sh[32];
    long long row = blockIdx.x;
    float* x = sc + row * (long long)SP_;
    float lv[5];
    float m = -1e30f;
    #pragma unroll
    for (int j = 0; j < 5; j++) {
        int c = threadIdx.x + j * 256;
        lv[j] = (c < S_) ? x[c] : -1e30f;
        m = fmaxf(m, lv[j]);
    }
    #pragma unroll
    for (int o = 16; o > 0; o >>= 1) m = fmaxf(m, __shfl_xor_sync(0xffffffffu, m, o));
    int lane = threadIdx.x & 31, w = threadIdx.x >> 5;
    if (lane == 0) sh[w] = m;
    __syncthreads();
    if (w == 0) {
        float t = lane < 8 ? sh[lane] : -1e30f;
        #pragma unroll
        for (int o = 4; o > 0; o >>= 1) t = fmaxf(t, __shfl_xor_sync(0xffffffffu, t, o));
        if (lane == 0) sh[0] = t;
    }
    __syncthreads();
    m = sh[0];
    __syncthreads();
    float s = 0.f;
    #pragma unroll
    for (int j = 0; j < 5; j++) {
        int c = threadIdx.x + j * 256;
        if (c < S_) { lv[j] = expf(lv[j] - m); s += lv[j]; }
    }
    #pragma unroll
    for (int o = 16; o > 0; o >>= 1) s += __shfl_xor_sync(0xffffffffu, s, o);
    if (lane == 0) sh[w] = s;
    __syncthreads();
    if (w == 0) {
        float t = lane < 8 ? sh[lane] : 0.f;
        #pragma unroll
        for (int o = 4; o > 0; o >>= 1) t += __shfl_xor_sync(0xffffffffu, t, o);
        if (lane == 0) sh[0] = t;
    }
    __syncthreads();
    float inv = 1.f / sh[0];
    #pragma unroll
    for (int j = 0; j < 5; j++) {
        int c = threadIdx.x + j * 256;
        if (c < S_) x[c] = lv[j] * inv;
    }
}

__global__ void swiglu_kernel(float* __restrict__ a1, const float* __restrict__ a3)
{
    long long t = (long long)blockIdx.x * blockDim.x + threadIdx.x;
    const long long total = (long long)B_ * S_ * FF_;
    if (t >= total) return;
    float x = a1[t];
    float sig = 1.f / (1.f + expf(-x));
    a1[t] = x * sig * a3[t];
}

// ================= host side =================
static inline void run_gemm(const float* A, const float* B, const float* bias, float* C,
                            int M, int N, int K, int lda, int ldb, int ldc,
                            int batch, int nH,
                            long long sAb, long long sAh, long long sBb, long long sBh,
                            long long sCb, long long sCh,
                            float alpha, bool accum)
{
    dim3 grid((N + 127) / 128, (M + 127) / 128, batch), block(256);
    bool hb = (bias != nullptr);
    if (accum)
        mma_gemm_kernel<true, true><<<grid, block>>>(
            A, B, bias, C, M, N, K, lda, ldb, ldc, nH, sAb, sAh, sBb, sBh, sCb, sCh, alpha);
    else if (hb)
        mma_gemm_kernel<false, true><<<grid, block>>>(
            A, B, bias, C, M, N, K, lda, ldb, ldc, nH, sAb, sAh, sBb, sBh, sCb, sCh, alpha);
    else
        mma_gemm_kernel<false, false><<<grid, block>>>(
            A, B, bias, C, M, N, K, lda, ldb, ldc, nH, sAb, sAh, sBb, sBh, sCb, sCh, alpha);
}

extern "C" void kernel_launch(void* const* d_in, const int* in_sizes, int n_in,
                              void* d_out, int out_size)
{
    (void)in_sizes; (void)n_in; (void)out_size;
    const float* x        = (const float*)d_in[0];
    const float* patch_w  = (const float*)d_in[1];
    const float* patch_b  = (const float*)d_in[2];
    const float* pln_g    = (const float*)d_in[3];
    const float* pln_b    = (const float*)d_in[4];
    const float* cls_tok  = (const float*)d_in[5];
    const float* ln1_g    = (const float*)d_in[6];
    const float* ln1_b    = (const float*)d_in[7];
    const float* wq       = (const float*)d_in[8];
    const float* bq       = (const float*)d_in[9];
    const float* wk       = (const float*)d_in[10];
    const float* bk       = (const float*)d_in[11];
    const float* wv       = (const float*)d_in[12];
    const float* bv       = (const float*)d_in[13];
    const float* wo       = (const float*)d_in[14];
    const float* bo       = (const float*)d_in[15];
    const float* ln2_g    = (const float*)d_in[16];
    const float* ln2_b    = (const float*)d_in[17];
    const float* w1       = (const float*)d_in[18];
    const float* b1       = (const float*)d_in[19];
    const float* w2       = (const float*)d_in[20];
    const float* b2       = (const float*)d_in[21];
    const float* w3       = (const float*)d_in[22];
    const float* b3       = (const float*)d_in[23];
    const float* lnf_g    = (const float*)d_in[24];
    const float* lnf_b    = (const float*)d_in[25];
    float* out = (float*)d_out;

    float *patches, *pe, *h, *y, *q, *k, *v, *o, *sc, *a1, *a3, *ct, *st;
    float *pwT, *wqT, *wkT, *wvT, *woT, *w1T, *w3T, *w2T, *vT;
    cudaGetSymbolAddress((void**)&patches, g_patches);
    cudaGetSymbolAddress((void**)&pe, g_pe);
    cudaGetSymbolAddress((void**)&h,  g_h);
    cudaGetSymbolAddress((void**)&y,  g_y);
    cudaGetSymbolAddress((void**)&q,  g_q);
    cudaGetSymbolAddress((void**)&k,  g_k);
    cudaGetSymbolAddress((void**)&v,  g_v);
    cudaGetSymbolAddress((void**)&o,  g_o);
    cudaGetSymbolAddress((void**)&sc, g_sc);
    cudaGetSymbolAddress((void**)&a1, g_a1);
    cudaGetSymbolAddress((void**)&a3, g_a3);
    cudaGetSymbolAddress((void**)&ct, g_cos);
    cudaGetSymbolAddress((void**)&st, g_sin);
    cudaGetSymbolAddress((void**)&pwT, g_pwT);
    cudaGetSymbolAddress((void**)&wqT, g_wqT);
    cudaGetSymbolAddress((void**)&wkT, g_wkT);
    cudaGetSymbolAddress((void**)&wvT, g_wvT);
    cudaGetSymbolAddress((void**)&woT, g_woT);
    cudaGetSymbolAddress((void**)&w1T, g_w1T);
    cudaGetSymbolAddress((void**)&w3T, g_w3T);
    cudaGetSymbolAddress((void**)&w2T, g_w2T);
    cudaGetSymbolAddress((void**)&vT,  g_vT);

    const int MR = B_ * S_;
    const long long SD  = (long long)S_ * D_;
    const long long SSP = (long long)S_ * SP_;

    dim3 tb(32, 8);

    // ---- weight transposes to [N,K] K-major ----
    transpose_kernel<<<dim3(32, 64, 1),  tb>>>(patch_w, pwT, NM_ * PS_, D_, 0, 0);
    transpose_kernel<<<dim3(32, 32, L_), tb>>>(wq, wqT, D_, D_, (long long)D_ * D_, (long long)D_ * D_);
    transpose_kernel<<<dim3(32, 32, L_), tb>>>(wk, wkT, D_, D_, (long long)D_ * D_, (long long)D_ * D_);
    transpose_kernel<<<dim3(32, 32, L_), tb>>>(wv, wvT, D_, D_, (long long)D_ * D_, (long long)D_ * D_);
    transpose_kernel<<<dim3(32, 32, L_), tb>>>(wo, woT, D_, D_, (long long)D_ * D_, (long long)D_ * D_);
    transpose_kernel<<<dim3(128, 32, L_), tb>>>(w1, w1T, D_, FF_, (long long)D_ * FF_, (long long)D_ * FF_);
    transpose_kernel<<<dim3(128, 32, L_), tb>>>(w3, w3T, D_, FF_, (long long)D_ * FF_, (long long)D_ * FF_);
    transpose_kernel<<<dim3(32, 128, L_), tb>>>(w2, w2T, FF_, D_, (long long)D_ * FF_, (long long)D_ * FF_);

    // ---- patchify + RoPE tables ----
    {
        long long n = (long long)B_ * NP_ * NM_ * PS_;
        patchify_kernel<<<(int)((n + 255) / 256), 256>>>(x, patches);
    }
    rope_table_kernel<<<(S_ * 32 + 255) / 256, 256>>>(ct, st);

    // ---- patch embed ----
    run_gemm(patches, pwT, patch_b, pe, B_ * NP_, D_, NM_ * PS_,
             NM_ * PS_, NM_ * PS_, D_, 1, 1, 0, 0, 0, 0, 0, 0, 1.f, false);
    patch_ln_kernel<<<B_ * NP_, 256>>>(pe, h, pln_g, pln_b);
    cls_kernel<<<(B_ * D_ + 255) / 256, 256>>>(h, cls_tok);

    const float scale = 0.125f;
    for (int l = 0; l < L_; l++) {
        const float* WqT = wqT + (size_t)l * D_ * D_;
        const float* WkT = wkT + (size_t)l * D_ * D_;
        const float* WvT = wvT + (size_t)l * D_ * D_;
        const float* WoT = woT + (size_t)l * D_ * D_;
        const float* W1T = w1T + (size_t)l * D_ * FF_;
        const float* W3T = w3T + (size_t)l * D_ * FF_;
        const float* W2T = w2T + (size_t)l * D_ * FF_;

        layernorm_kernel<<<MR, 256>>>(h, y, ln1_g + (size_t)l * D_, ln1_b + (size_t)l * D_);

        run_gemm(y, WqT, bq + (size_t)l * D_, q, MR, D_, D_, D_, D_, D_,
                 1, 1, 0, 0, 0, 0, 0, 0, 1.f, false);
        run_gemm(y, WkT, bk + (size_t)l * D_, k, MR, D_, D_, D_, D_, D_,
                 1, 1, 0, 0, 0, 0, 0, 0, 1.f, false);
        run_gemm(y, WvT, bv + (size_t)l * D_, v, MR, D_, D_, D_, D_, D_,
                 1, 1, 0, 0, 0, 0, 0, 0, 1.f, false);

        {
            long long n = (long long)B_ * S_ * H_ * (DH_ / 2);
            rope_kernel<<<(int)((n + 255) / 256), 256>>>(q, k, ct, st);
        }
        vtrans_kernel<<<dim3(33, 2, B_ * H_), tb>>>(v, vT);

        // scores = scale * q @ k^T  (k is [N,K] K-major per head)
        run_gemm(q, k, nullptr, sc, S_, S_, DH_, D_, D_, SP_,
                 B_ * H_, H_,
                 SD, DH_, SD, DH_, (long long)H_ * SSP, SSP,
                 scale, false);

        softmax_kernel<<<B_ * H_ * S_, 256>>>(sc);

        // o = attn @ v  (vT[bh] is [64, S] K-major, rows padded to SP_)
        run_gemm(sc, vT, nullptr, o, S_, DH_, S_, SP_, SP_, D_,
                 B_ * H_, H_,
                 (long long)H_ * SSP, SSP,
                 (long long)H_ * DH_ * SP_, (long long)DH_ * SP_,
                 SD, DH_, 1.f, false);

        // h += o @ Wo + bo
        run_gemm(o, WoT, bo + (size_t)l * D_, h, MR, D_, D_, D_, D_, D_,
                 1, 1, 0, 0, 0, 0, 0, 0, 1.f, true);

        layernorm_kernel<<<MR, 256>>>(h, y, ln2_g + (size_t)l * D_, ln2_b + (size_t)l * D_);

        run_gemm(y, W1T, b1 + (size_t)l * FF_, a1, MR, FF_, D_, D_, D_, FF_,
                 1, 1, 0, 0, 0, 0, 0, 0, 1.f, false);
        run_gemm(y, W3T, b3 + (size_t)l * FF_, a3, MR, FF_, D_, D_, D_, FF_,
                 1, 1, 0, 0, 0, 0, 0, 0, 1.f, false);

        {
            long long n = (long long)B_ * S_ * FF_;
            swiglu_kernel<<<(int)((n + 255) / 256), 256>>>(a1, a3);
        }

        // h += swiglu @ W2 + b2
        run_gemm(a1, W2T, b2 + (size_t)l * D_, h, MR, D_, FF_, FF_, FF_, D_,
                 1, 1, 0, 0, 0, 0, 0, 0, 1.f, true);
    }

    layernorm_kernel<<<MR, 256>>>(h, out, lnf_g, lnf_b);
}